// round 3
// baseline (speedup 1.0000x reference)
#include <cuda_runtime.h>
#include <cstdint>

typedef unsigned long long ull;

#define BATCH 8192
#define HID 128
#define TSTEPS 64

// ---------------- scratch (device globals; no allocations allowed) ----------
__device__ float g_hA[BATCH * HID];
__device__ float g_hB[BATCH * HID];
__device__ float g_x2[BATCH * HID];
__device__ float g_zc[BATCH * HID];

// ---------------- packed f32x2 helpers --------------------------------------
__device__ __forceinline__ ull pk2(float a, float b) {
    ull r;
    asm("mov.b64 %0, {%1,%2};" : "=l"(r) : "f"(a), "f"(b));
    return r;
}
__device__ __forceinline__ void upk2(ull v, float& a, float& b) {
    asm("mov.b64 {%0,%1}, %2;" : "=f"(a), "=f"(b) : "l"(v));
}
__device__ __forceinline__ void fma2(ull& d, ull a, ull b) {
    asm("fma.rn.f32x2 %0, %1, %2, %0;" : "+l"(d) : "l"(a), "l"(b));
}

__device__ __forceinline__ float sigf(float x)  { return 1.0f / (1.0f + __expf(-x)); }
__device__ __forceinline__ float tanhfast(float x) { return 2.0f / (1.0f + __expf(-2.0f * x)) - 1.0f; }

// ---------------- tiling constants ------------------------------------------
constexpr int HP  = 132;   // smem stride for transposed h / x tiles (mult of 4)
constexpr int WPE = 98;    // smem stride for enc weight tiles (96 feats, even)
constexpr int WPD = 194;   // smem stride for dec weight tiles (192 feats, even)

constexpr int ENC_SMEM = (128 * HP + 29 * HP + 128 * WPE + 29 * WPE) * 4; // 144440
constexpr int DEC_SMEM = (128 * HP + 128 * WPD) * 4;                      // 166912
constexpr int CONV_SMEM = (16 * 1728 + 3888 + 2048 + 16 * 144) * 4;       // 143552

// =============================================================================
// Encoder GRU step: h' = GRU(x_t, h) with x_t (B,29), h (B,128)
// Block: 128 rows x 32 features(all 3 gates). 512 threads.
// Thread: 4 rows x 2 features x (3 gx + 3 gh) accumulators, f32x2-packed over
// the feature pair.
// =============================================================================
template <bool FIRST>
__global__ void __launch_bounds__(512, 1)
enc_step_k(const float* __restrict__ hin, float* __restrict__ hout,
           const float* __restrict__ lin,
           const float* __restrict__ Wih, const float* __restrict__ Whh,
           const float* __restrict__ bih, const float* __restrict__ bhh, int t)
{
    extern __shared__ float sm[];
    float* sH  = sm;                 // [k=128][row=128] stride HP
    float* sX  = sH + 128 * HP;      // [k=29][row=128]  stride HP
    float* sWh = sX + 29 * HP;       // [k=128][feat=96] stride WPE
    float* sWi = sWh + 128 * WPE;    // [k=29][feat=96]  stride WPE

    const int tid  = threadIdx.x;
    const int j0   = blockIdx.x * 32;
    const int row0 = blockIdx.y * 128;

    if (!FIRST) {
        for (int idx = tid; idx < 128 * 128; idx += 512) {
            int r = idx >> 7, k = idx & 127;
            sH[k * HP + r] = hin[(size_t)(row0 + r) * HID + k];
        }
    }
    for (int idx = tid; idx < 128 * 32; idx += 512) {
        int r = idx >> 5, k = idx & 31;
        if (k < 29)
            sX[k * HP + r] = lin[(size_t)(row0 + r) * (TSTEPS * 29) + (size_t)t * 29 + k];
    }
    if (!FIRST) {
        for (int idx = tid; idx < 96 * 128; idx += 512) {
            int f = idx >> 7, k = idx & 127;
            int s = f >> 5, fi = f & 31;
            sWh[k * WPE + f] = Whh[(size_t)(s * HID + j0 + fi) * HID + k];
        }
    }
    for (int idx = tid; idx < 96 * 32; idx += 512) {
        int f = idx >> 5, k = idx & 31;
        int s = f >> 5, fi = f & 31;
        if (k < 29)
            sWi[k * WPE + f] = Wih[(size_t)(s * HID + j0 + fi) * 29 + k];
    }
    __syncthreads();

    const int fp = tid & 15;
    const int rg = tid >> 4;
    const int jA = j0 + 2 * fp;

    ull accX[3][4], accH[3][4];
#pragma unroll
    for (int s = 0; s < 3; ++s) {
        ull bx = *(const ull*)(bih + s * HID + jA);
        ull bh = *(const ull*)(bhh + s * HID + jA);
#pragma unroll
        for (int rr = 0; rr < 4; ++rr) { accX[s][rr] = bx; accH[s][rr] = bh; }
    }

    if (!FIRST) {
#pragma unroll 4
        for (int k = 0; k < 128; ++k) {
            float4 hv = *(const float4*)(sH + k * HP + rg * 4);
            ull h0 = pk2(hv.x, hv.x), h1 = pk2(hv.y, hv.y);
            ull h2 = pk2(hv.z, hv.z), h3 = pk2(hv.w, hv.w);
#pragma unroll
            for (int s = 0; s < 3; ++s) {
                ull wv = *(const ull*)(sWh + k * WPE + s * 32 + 2 * fp);
                fma2(accH[s][0], h0, wv); fma2(accH[s][1], h1, wv);
                fma2(accH[s][2], h2, wv); fma2(accH[s][3], h3, wv);
            }
        }
    }
#pragma unroll 4
    for (int k = 0; k < 29; ++k) {
        float4 xv = *(const float4*)(sX + k * HP + rg * 4);
        ull x0 = pk2(xv.x, xv.x), x1 = pk2(xv.y, xv.y);
        ull x2 = pk2(xv.z, xv.z), x3 = pk2(xv.w, xv.w);
#pragma unroll
        for (int s = 0; s < 3; ++s) {
            ull wv = *(const ull*)(sWi + k * WPE + s * 32 + 2 * fp);
            fma2(accX[s][0], x0, wv); fma2(accX[s][1], x1, wv);
            fma2(accX[s][2], x2, wv); fma2(accX[s][3], x3, wv);
        }
    }

#pragma unroll
    for (int rr = 0; rr < 4; ++rr) {
        int r = rg * 4 + rr;
        float xr0, xr1, xz0, xz1, xn0, xn1, hr0, hr1, hz0, hz1, hn0, hn1;
        upk2(accX[0][rr], xr0, xr1); upk2(accX[1][rr], xz0, xz1); upk2(accX[2][rr], xn0, xn1);
        upk2(accH[0][rr], hr0, hr1); upk2(accH[1][rr], hz0, hz1); upk2(accH[2][rr], hn0, hn1);
        float rg0 = sigf(xr0 + hr0), rg1 = sigf(xr1 + hr1);
        float z0  = sigf(xz0 + hz0), z1  = sigf(xz1 + hz1);
        float n0  = tanhfast(xn0 + rg0 * hn0), n1 = tanhfast(xn1 + rg1 * hn1);
        float hp0 = FIRST ? 0.0f : sH[jA * HP + r];
        float hp1 = FIRST ? 0.0f : sH[(jA + 1) * HP + r];
        float2 o;
        o.x = (1.0f - z0) * n0 + z0 * hp0;
        o.y = (1.0f - z1) * n1 + z1 * hp1;
        *(float2*)(hout + (size_t)(row0 + r) * HID + jA) = o;
    }
}

// =============================================================================
// Decoder GRU step. For t>=2 the GRU input equals h, so gx and gh are a single
// fused (B,128)@(128,768) GEMM. FIRST (t=1): xin = 0 -> gx = bih only.
// =============================================================================
template <bool FIRST>
__global__ void __launch_bounds__(512, 1)
dec_step_k(const float* __restrict__ hin, float* __restrict__ hout,
           const float* __restrict__ Wih, const float* __restrict__ Whh,
           const float* __restrict__ bih, const float* __restrict__ bhh)
{
    extern __shared__ float sm[];
    float* sH = sm;               // [k=128][row=128] stride HP
    float* sW = sH + 128 * HP;    // [k=128][feat=192] stride WPD (sec0-2 Wih, 3-5 Whh)

    const int tid  = threadIdx.x;
    const int j0   = blockIdx.x * 32;
    const int row0 = blockIdx.y * 128;

    for (int idx = tid; idx < 128 * 128; idx += 512) {
        int r = idx >> 7, k = idx & 127;
        sH[k * HP + r] = hin[(size_t)(row0 + r) * HID + k];
    }
    for (int idx = tid; idx < 192 * 128; idx += 512) {
        int f = idx >> 7, k = idx & 127;
        int s = f >> 5, fi = f & 31;
        if (FIRST && s < 3) continue;
        const float* W = (s < 3) ? Wih : Whh;
        sW[k * WPD + f] = W[(size_t)((s % 3) * HID + j0 + fi) * HID + k];
    }
    __syncthreads();

    const int fp = tid & 15;
    const int rg = tid >> 4;
    const int jA = j0 + 2 * fp;

    ull acc[6][4];
#pragma unroll
    for (int s = 0; s < 6; ++s) {
        const float* bb = (s < 3) ? bih : bhh;
        ull bv = *(const ull*)(bb + (s % 3) * HID + jA);
#pragma unroll
        for (int rr = 0; rr < 4; ++rr) acc[s][rr] = bv;
    }

#pragma unroll 4
    for (int k = 0; k < 128; ++k) {
        float4 hv = *(const float4*)(sH + k * HP + rg * 4);
        ull h0 = pk2(hv.x, hv.x), h1 = pk2(hv.y, hv.y);
        ull h2 = pk2(hv.z, hv.z), h3 = pk2(hv.w, hv.w);
#pragma unroll
        for (int s = 0; s < 6; ++s) {
            if (FIRST && s < 3) continue;
            ull wv = *(const ull*)(sW + k * WPD + s * 32 + 2 * fp);
            fma2(acc[s][0], h0, wv); fma2(acc[s][1], h1, wv);
            fma2(acc[s][2], h2, wv); fma2(acc[s][3], h3, wv);
        }
    }

#pragma unroll
    for (int rr = 0; rr < 4; ++rr) {
        int r = rg * 4 + rr;
        float xr0, xr1, xz0, xz1, xn0, xn1, hr0, hr1, hz0, hz1, hn0, hn1;
        upk2(acc[0][rr], xr0, xr1); upk2(acc[1][rr], xz0, xz1); upk2(acc[2][rr], xn0, xn1);
        upk2(acc[3][rr], hr0, hr1); upk2(acc[4][rr], hz0, hz1); upk2(acc[5][rr], hn0, hn1);
        float rg0 = sigf(xr0 + hr0), rg1 = sigf(xr1 + hr1);
        float z0  = sigf(xz0 + hz0), z1  = sigf(xz1 + hz1);
        float n0  = tanhfast(xn0 + rg0 * hn0), n1 = tanhfast(xn1 + rg1 * hn1);
        float hp0 = sH[jA * HP + r];
        float hp1 = sH[(jA + 1) * HP + r];
        float2 o;
        o.x = (1.0f - z0) * n0 + z0 * hp0;
        o.y = (1.0f - z1) * n1 + z1 * hp1;
        *(float2*)(hout + (size_t)(row0 + r) * HID + jA) = o;
    }
}

// =============================================================================
// CNN: conv1 (27->16, 3x3, s2) + relu + conv2 (16->32, 2x2, s1) + relu,
// flattened CHW to g_x2 (B,128). 16 batch elems per block, 256 threads.
// =============================================================================
__global__ void __launch_bounds__(256, 1)
conv_k(const float* __restrict__ cnn,
       const float* __restrict__ w1, const float* __restrict__ b1,
       const float* __restrict__ w2, const float* __restrict__ b2)
{
    extern __shared__ float sm[];
    float* sin_ = sm;                  // [16][8][8][27]
    float* sw1  = sin_ + 16 * 1728;    // 3888
    float* sw2  = sw1 + 3888;          // 2048
    float* sx1  = sw2 + 2048;          // [16][16][3][3]

    const int tid = threadIdx.x;
    const int b0  = blockIdx.x * 16;

    for (int i = tid; i < 16 * 1728; i += 256) sin_[i] = cnn[(size_t)b0 * 1728 + i];
    for (int i = tid; i < 3888; i += 256) sw1[i] = w1[i];
    for (int i = tid; i < 2048; i += 256) sw2[i] = w2[i];
    __syncthreads();

    const int bb = tid >> 4;
    const int c  = tid & 15;

    // conv1: thread computes all 9 spatial outputs for (bb, c)
    float acc[9];
    float bc = b1[c];
#pragma unroll
    for (int p = 0; p < 9; ++p) acc[p] = bc;
    for (int ky = 0; ky < 3; ++ky)
        for (int kx = 0; kx < 3; ++kx)
            for (int ic = 0; ic < 27; ++ic) {
                float w = sw1[c * 243 + ic * 9 + ky * 3 + kx];
#pragma unroll
                for (int i = 0; i < 3; ++i)
#pragma unroll
                    for (int j = 0; j < 3; ++j)
                        acc[i * 3 + j] = fmaf(sin_[((bb * 8 + 2 * i + ky) * 8 + 2 * j + kx) * 27 + ic],
                                              w, acc[i * 3 + j]);
            }
#pragma unroll
    for (int p = 0; p < 9; ++p) sx1[(bb * 16 + c) * 9 + p] = fmaxf(acc[p], 0.0f);
    __syncthreads();

    // conv2: thread computes c2 in {c, c+16}, all 4 spatial positions
    float a2[2][4];
#pragma unroll
    for (int q = 0; q < 2; ++q) {
        float bcc = b2[c + 16 * q];
#pragma unroll
        for (int p = 0; p < 4; ++p) a2[q][p] = bcc;
    }
    for (int ci = 0; ci < 16; ++ci) {
        float xv[9];
#pragma unroll
        for (int p = 0; p < 9; ++p) xv[p] = sx1[(bb * 16 + ci) * 9 + p];
#pragma unroll
        for (int q = 0; q < 2; ++q) {
            int c2 = c + 16 * q;
#pragma unroll
            for (int ky = 0; ky < 2; ++ky)
#pragma unroll
                for (int kx = 0; kx < 2; ++kx) {
                    float w = sw2[(c2 * 16 + ci) * 4 + ky * 2 + kx];
#pragma unroll
                    for (int i = 0; i < 2; ++i)
#pragma unroll
                        for (int j = 0; j < 2; ++j)
                            a2[q][i * 2 + j] = fmaf(xv[(i + ky) * 3 + (j + kx)], w, a2[q][i * 2 + j]);
                }
        }
    }
    float* outp = g_x2 + (size_t)(b0 + bb) * 128;
#pragma unroll
    for (int q = 0; q < 2; ++q)
#pragma unroll
        for (int p = 0; p < 4; ++p)
            outp[(c + 16 * q) * 4 + p] = fmaxf(a2[q][p], 0.0f);
}

// fc: z_cnn = relu(g_x2 @ fc_w^T + fc_b)
__global__ void fc_k(const float* __restrict__ W, const float* __restrict__ bias)
{
    int gid = blockIdx.x * 256 + threadIdx.x;
    int b = gid >> 7, j = gid & 127;
    const float* xr = g_x2 + (size_t)b * 128;
    const float* wr = W + (size_t)j * 128;
    float acc = bias[j];
#pragma unroll 8
    for (int k = 0; k < 128; ++k) acc = fmaf(xr[k], wr[k], acc);
    g_zc[gid] = fmaxf(acc, 0.0f);
}

// heads: out[0:B*78] = distris, out[B*78:B*79] = value
__global__ void heads_k(const float* __restrict__ hfin,
                        const float* __restrict__ dw, const float* __restrict__ db,
                        const float* __restrict__ vw, const float* __restrict__ vb,
                        float* __restrict__ out)
{
    int lane = threadIdx.x % 80;
    int b = blockIdx.x * 2 + threadIdx.x / 80;
    if (lane >= 79) return;
    const float* w = (lane < 78) ? (dw + (size_t)lane * 256) : vw;
    float acc = (lane < 78) ? db[lane] : vb[0];
    const float* z = g_zc + (size_t)b * 128;
    const float* h = hfin + (size_t)b * 128;
#pragma unroll 8
    for (int k = 0; k < 128; ++k) acc = fmaf(z[k], w[k], acc);
#pragma unroll 8
    for (int k = 0; k < 128; ++k) acc = fmaf(h[k], w[128 + k], acc);
    if (lane < 78) out[(size_t)b * 78 + lane] = acc;
    else           out[(size_t)BATCH * 78 + b] = acc;
}

// =============================================================================
extern "C" void kernel_launch(void* const* d_in, const int* in_sizes, int n_in,
                              void* d_out, int out_size)
{
    const float* cnn  = (const float*)d_in[0];
    const float* lin  = (const float*)d_in[1];
    const float* c1w  = (const float*)d_in[2];
    const float* c1b  = (const float*)d_in[3];
    const float* c2w  = (const float*)d_in[4];
    const float* c2b  = (const float*)d_in[5];
    const float* fcw  = (const float*)d_in[6];
    const float* fcb  = (const float*)d_in[7];
    const float* eWih = (const float*)d_in[8];
    const float* eWhh = (const float*)d_in[9];
    const float* ebih = (const float*)d_in[10];
    const float* ebhh = (const float*)d_in[11];
    const float* dWih = (const float*)d_in[12];
    const float* dWhh = (const float*)d_in[13];
    const float* dbih = (const float*)d_in[14];
    const float* dbhh = (const float*)d_in[15];
    const float* disw = (const float*)d_in[16];
    const float* disb = (const float*)d_in[17];
    const float* vw   = (const float*)d_in[18];
    const float* vb   = (const float*)d_in[19];
    float* out = (float*)d_out;

    float *hA, *hB;
    cudaGetSymbolAddress((void**)&hA, g_hA);
    cudaGetSymbolAddress((void**)&hB, g_hB);

    cudaFuncSetAttribute(conv_k, cudaFuncAttributeMaxDynamicSharedMemorySize, CONV_SMEM);
    cudaFuncSetAttribute(enc_step_k<true>,  cudaFuncAttributeMaxDynamicSharedMemorySize, ENC_SMEM);
    cudaFuncSetAttribute(enc_step_k<false>, cudaFuncAttributeMaxDynamicSharedMemorySize, ENC_SMEM);
    cudaFuncSetAttribute(dec_step_k<true>,  cudaFuncAttributeMaxDynamicSharedMemorySize, DEC_SMEM);
    cudaFuncSetAttribute(dec_step_k<false>, cudaFuncAttributeMaxDynamicSharedMemorySize, DEC_SMEM);

    // CNN branch
    conv_k<<<BATCH / 16, 256, CONV_SMEM>>>(cnn, c1w, c1b, c2w, c2b);
    fc_k<<<BATCH * 128 / 256, 256>>>(fcw, fcb);

    dim3 sg(4, BATCH / 128);

    // encoder: t=0 has h=0 (skip Whh GEMM)
    enc_step_k<true><<<sg, 512, ENC_SMEM>>>(nullptr, hA, lin, eWih, eWhh, ebih, ebhh, 0);
    for (int t = 1; t < TSTEPS; ++t) {
        const float* in = (t & 1) ? hA : hB;
        float* o        = (t & 1) ? hB : hA;
        enc_step_k<false><<<sg, 512, ENC_SMEM>>>(in, o, lin, eWih, eWhh, ebih, ebhh, t);
    }
    // h_enc now in hB (t=63 wrote hB)

    // decoder: step 0 has xin=0 (gx = bih); steps >=1 have xin == h
    dec_step_k<true><<<sg, 512, DEC_SMEM>>>(hB, hA, dWih, dWhh, dbih, dbhh);
    for (int d = 1; d < TSTEPS; ++d) {
        const float* in = (d & 1) ? hA : hB;
        float* o        = (d & 1) ? hB : hA;
        dec_step_k<false><<<sg, 512, DEC_SMEM>>>(in, o, dWih, dWhh, dbih, dbhh);
    }
    // z_pn now in hB (d=63 wrote hB)

    heads_k<<<BATCH / 2, 160>>>(hB, disw, disb, vw, vb, out);
}